// round 1
// baseline (speedup 1.0000x reference)
#include <cuda_runtime.h>

typedef unsigned long long ull;

#define NN   10000
#define TT   64
#define NIN  64
#define NH   128
#define NOUT 64
#define KTOT 192          // NIN + NH
#define NG   512          // 4 gates * NH
#define EMAX 160000

// ---------------- device scratch (static, no allocation) ----------------
__device__ float d_dinv[NN];
__device__ int   d_deg[NN];
__device__ int   d_off[NN + 1];
__device__ int   d_fill[NN];
__device__ int   d_adj[EMAX];
__device__ float d_Px[(size_t)TT * NN * NIN];   // P @ x_t, all t   (~164 MB)
__device__ float d_h[NN * NH];
__device__ float d_c[NN * NH];
__device__ float d_hs[NN * NH];                 // dinv * h (pre-scaled for prop)
__device__ float d_Ph[NN * NH];                 // P @ h
__device__ float d_Wall[KTOT * NG];             // packed gate weights [k][g*128+j]
__device__ float d_ball[NG];
__device__ float d_W1p[NH * 256];               // packed W1:  [k][Ha cols | Hb cols]
__device__ float d_Wcp[NH * NOUT];              // packed Wc^T
__device__ float d_HaHb[NN * 256];
__device__ float d_nodes[NN * NH];
__device__ float d_Pn[NN * NH];

// ---------------- small helpers ----------------
__device__ __forceinline__ ull pk2(float x, float y) {
    ull r; asm("mov.b64 %0, {%1,%2};" : "=l"(r) : "f"(x), "f"(y)); return r;
}
__device__ __forceinline__ void upk2(ull v, float& x, float& y) {
    asm("mov.b64 {%0,%1}, %2;" : "=f"(x), "=f"(y) : "l"(v));
}
// packed fp32x2 FMA: d = a*b + d  (full-rate fp32 on sm_103a)
__device__ __forceinline__ void fma2(ull& d, ull a, ull b) {
    asm("fma.rn.f32x2 %0, %1, %2, %0;" : "+l"(d) : "l"(a), "l"(b));
}
__device__ __forceinline__ float sigf(float x) {
    return 1.0f / (1.0f + __expf(-x));
}

// ---------------- setup kernels ----------------
__global__ void k_init() {
    int i = blockIdx.x * blockDim.x + threadIdx.x;
    if (i < NN * NH) { d_h[i] = 0.f; d_c[i] = 0.f; d_hs[i] = 0.f; }
    if (i < NN)      { d_deg[i] = 1; d_fill[i] = 0; }
}

__global__ void k_deg(const int* __restrict__ dst, int E) {
    int i = blockIdx.x * blockDim.x + threadIdx.x;
    if (i < E) atomicAdd(&d_deg[dst[i]], 1);
}

__global__ void k_dinv() {
    int i = blockIdx.x * blockDim.x + threadIdx.x;
    if (i < NN) d_dinv[i] = rsqrtf((float)d_deg[i]);
}

// exclusive scan of (deg-1) -> CSR row offsets; single block of 1024 threads
__global__ void k_scan(int E) {
    __shared__ int ssum[1024];
    int tid = threadIdx.x;
    int loc[10]; int run = 0;
#pragma unroll
    for (int i = 0; i < 10; i++) {
        int v = tid * 10 + i;
        int c = (v < NN) ? (d_deg[v] - 1) : 0;
        loc[i] = run; run += c;
    }
    ssum[tid] = run; __syncthreads();
    for (int off = 1; off < 1024; off <<= 1) {
        int t = (tid >= off) ? ssum[tid - off] : 0;
        __syncthreads();
        ssum[tid] += t;
        __syncthreads();
    }
    int base = (tid == 0) ? 0 : ssum[tid - 1];
#pragma unroll
    for (int i = 0; i < 10; i++) {
        int v = tid * 10 + i;
        if (v < NN) d_off[v] = base + loc[i];
    }
    if (tid == 0) d_off[NN] = E;
}

__global__ void k_fill(const int* __restrict__ src, const int* __restrict__ dst, int E) {
    int i = blockIdx.x * blockDim.x + threadIdx.x;
    if (i < E) {
        int v = dst[i];
        int p = d_off[v] + atomicAdd(&d_fill[v], 1);
        d_adj[p] = src[i];
    }
}

// pack weights into GEMM-friendly layouts
__global__ void k_pack(const float* __restrict__ Wi, const float* __restrict__ Wf,
                       const float* __restrict__ Wo, const float* __restrict__ Wg,
                       const float* __restrict__ bi, const float* __restrict__ bf,
                       const float* __restrict__ bo, const float* __restrict__ bg,
                       const float* __restrict__ W1, const float* __restrict__ Wc) {
    int idx = blockIdx.x * blockDim.x + threadIdx.x;
    if (idx < KTOT * NG) {
        int k = idx / NG, col = idx % NG;
        int g = col >> 7, j = col & 127;
        const float* W = (g == 0) ? Wi : (g == 1) ? Wf : (g == 2) ? Wo : Wg;
        d_Wall[idx] = W[j * KTOT + k];
        if (idx < NG) {
            const float* b = (g == 0) ? bi : (g == 1) ? bf : (g == 2) ? bo : bg;
            d_ball[idx] = b[j];
        }
    } else {
        int r = idx - KTOT * NG;
        if (r < NH * 256) {
            int k = r / 256, c = r % 256;
            d_W1p[r] = W1[(c & 127) * 256 + (c >> 7) * 128 + k];
        } else {
            r -= NH * 256;
            if (r < NH * NOUT) {
                int k = r / NOUT, j = r % NOUT;
                d_Wcp[r] = Wc[j * NH + k];
            }
        }
    }
}

// Px[t,v] = dinv[v] * ( sum_{e in in(v)} dinv[src]*x[t,src] + dinv[v]*x[t,v] )
// one warp per (t, v); float2 per lane (64 feats)
__global__ void k_px(const float* __restrict__ x) {
    int w = blockIdx.x * 8 + (threadIdx.x >> 5);
    int t = w / NN, v = w - t * NN;
    int l2 = (threadIdx.x & 31) * 2;
    const float* xt = x + (size_t)t * NN * NIN;
    float2 a = make_float2(0.f, 0.f);
    int e = d_off[v], end = d_off[v + 1];
#pragma unroll 4
    for (; e < end; e++) {
        int s = d_adj[e];
        float ds = d_dinv[s];
        float2 xv = *(const float2*)&xt[s * NIN + l2];
        a.x += ds * xv.x; a.y += ds * xv.y;
    }
    float dv = d_dinv[v];
    float2 xs = *(const float2*)&xt[v * NIN + l2];
    a.x += dv * xs.x; a.y += dv * xs.y;
    a.x *= dv; a.y *= dv;
    *(float2*)&d_Px[((size_t)t * NN + v) * NIN + l2] = a;
}

// Ph[v] = dinv[v] * ( sum_{in-edges} hs[src] + hs[v] )   (hs pre-scaled by dinv)
__global__ void k_prop() {
    int w = blockIdx.x * 8 + (threadIdx.x >> 5);
    if (w >= NN) return;
    int l4 = (threadIdx.x & 31) * 4;
    float4 acc = *(const float4*)&d_hs[w * NH + l4];   // self-loop term
    int e = d_off[w], end = d_off[w + 1];
    for (; e + 1 < end; e += 2) {
        int s0 = d_adj[e], s1 = d_adj[e + 1];
        float4 v0 = *(const float4*)&d_hs[s0 * NH + l4];
        float4 v1 = *(const float4*)&d_hs[s1 * NH + l4];
        acc.x += v0.x + v1.x; acc.y += v0.y + v1.y;
        acc.z += v0.z + v1.z; acc.w += v0.w + v1.w;
    }
    if (e < end) {
        int s0 = d_adj[e];
        float4 v0 = *(const float4*)&d_hs[s0 * NH + l4];
        acc.x += v0.x; acc.y += v0.y; acc.z += v0.z; acc.w += v0.w;
    }
    float dv = d_dinv[w];
    acc.x *= dv; acc.y *= dv; acc.z *= dv; acc.w *= dv;
    *(float4*)&d_Ph[w * NH + l4] = acc;
}

// fused GEMM + LSTM gates:
//   pre[m, 0:512] = Px[t,m,:] @ Wall[0:64,:] + Ph[m,:] @ Wall[64:192,:] + ball
//   i,f,o,g -> c,h update, hs = dinv*h
// block: BM=64 rows x BN=256 cols (all 4 gates, 64 j-columns). grid (157, 2).
__global__ void __launch_bounds__(256, 2) k_gg(int t) {
    __shared__ __align__(16) float As[16][64];
    __shared__ __align__(16) float Bs[16][256];
    const int tid = threadIdx.x;
    const int tx = tid & 31, ty = tid >> 5;
    const int m0 = blockIdx.x * 64;
    const int j0 = blockIdx.y * 64;

    ull acc[8][4];
#pragma unroll
    for (int i = 0; i < 8; i++)
#pragma unroll
        for (int g = 0; g < 4; g++) acc[i][g] = 0ull;

    const int lrow = tid >> 2;
    const int lkp  = (tid & 3) * 4;
    const int grow = m0 + lrow;

    for (int kc = 0; kc < KTOT; kc += 16) {
        float4 av = make_float4(0.f, 0.f, 0.f, 0.f);
        if (grow < NN) {
            if (kc < NIN) av = *(const float4*)&d_Px[((size_t)t * NN + grow) * NIN + kc + lkp];
            else          av = *(const float4*)&d_Ph[grow * NH + (kc - NIN) + lkp];
        }
        As[lkp + 0][lrow] = av.x; As[lkp + 1][lrow] = av.y;
        As[lkp + 2][lrow] = av.z; As[lkp + 3][lrow] = av.w;
#pragma unroll
        for (int r = 0; r < 4; r++) {
            int q = tid + r * 256;
            int k = q >> 6;
            int cl = (q & 63) * 4;   // local col: [gate(2b) | j(6b)]*4
            float4 bv = *(const float4*)&d_Wall[(kc + k) * NG + (cl >> 6) * 128 + j0 + (cl & 63)];
            *(float4*)&Bs[k][cl] = bv;
        }
        __syncthreads();
#pragma unroll
        for (int k = 0; k < 16; k++) {
            float4 a0 = *(const float4*)&As[k][ty * 8];
            float4 a1 = *(const float4*)&As[k][ty * 8 + 4];
            ull a2[8];
            a2[0] = pk2(a0.x, a0.x); a2[1] = pk2(a0.y, a0.y);
            a2[2] = pk2(a0.z, a0.z); a2[3] = pk2(a0.w, a0.w);
            a2[4] = pk2(a1.x, a1.x); a2[5] = pk2(a1.y, a1.y);
            a2[6] = pk2(a1.z, a1.z); a2[7] = pk2(a1.w, a1.w);
            ull b2[4];
#pragma unroll
            for (int g = 0; g < 4; g++) b2[g] = *(const ull*)&Bs[k][g * 64 + tx * 2];
#pragma unroll
            for (int tm = 0; tm < 8; tm++)
#pragma unroll
                for (int g = 0; g < 4; g++) fma2(acc[tm][g], a2[tm], b2[g]);
        }
        __syncthreads();
    }

    float2 bias[4];
#pragma unroll
    for (int g = 0; g < 4; g++) bias[g] = *(const float2*)&d_ball[g * 128 + j0 + tx * 2];

#pragma unroll
    for (int tm = 0; tm < 8; tm++) {
        int m = m0 + ty * 8 + tm;
        if (m >= NN) continue;
        float dv = d_dinv[m];
        int cidx = m * NH + j0 + tx * 2;
        float2 cold = *(const float2*)&d_c[cidx];
        float pre[4][2];
#pragma unroll
        for (int g = 0; g < 4; g++) {
            upk2(acc[tm][g], pre[g][0], pre[g][1]);
            pre[g][0] += bias[g].x; pre[g][1] += bias[g].y;
        }
        float cv[2], hv[2], hsv[2];
#pragma unroll
        for (int p = 0; p < 2; p++) {
            float i_ = sigf(pre[0][p]);
            float f_ = sigf(pre[1][p]);
            float o_ = sigf(pre[2][p]);
            float g_ = tanhf(pre[3][p]);
            float co = p ? cold.y : cold.x;
            float cn = f_ * co + i_ * g_;
            float hh = o_ * tanhf(cn);
            cv[p] = cn; hv[p] = hh; hsv[p] = dv * hh;
        }
        *(float2*)&d_c[cidx]  = make_float2(cv[0], cv[1]);
        *(float2*)&d_h[cidx]  = make_float2(hv[0], hv[1]);
        *(float2*)&d_hs[cidx] = make_float2(hsv[0], hsv[1]);
    }
}

// generic small GEMM: C[M,N] = A[M,K] @ B[K,N] (+bias). sel picks device buffers.
__global__ void k_gemm(int sel, const float* __restrict__ bias, float* __restrict__ Cout,
                       int M, int K, int N) {
    __shared__ __align__(16) float As[16][64];
    __shared__ __align__(16) float Bs[16][64];
    const float* A = sel ? d_Pn  : d_h;
    const float* B = sel ? d_Wcp : d_W1p;
    float*       C = sel ? Cout  : d_HaHb;
    int tid = threadIdx.x;
    int tx = tid & 15, ty = tid >> 4;
    int m0 = blockIdx.x * 64, n0 = blockIdx.y * 64;
    float acc[4][4] = {};
    int lrow = tid >> 2, lkp = (tid & 3) * 4;
    int bk = tid >> 4, bcc = (tid & 15) * 4;
    for (int kc = 0; kc < K; kc += 16) {
        float4 av = make_float4(0.f, 0.f, 0.f, 0.f);
        int grow = m0 + lrow;
        if (grow < M) av = *(const float4*)&A[grow * K + kc + lkp];
        As[lkp + 0][lrow] = av.x; As[lkp + 1][lrow] = av.y;
        As[lkp + 2][lrow] = av.z; As[lkp + 3][lrow] = av.w;
        float4 bv = *(const float4*)&B[(kc + bk) * N + n0 + bcc];
        *(float4*)&Bs[bk][bcc] = bv;
        __syncthreads();
#pragma unroll
        for (int k = 0; k < 16; k++) {
            float4 a = *(const float4*)&As[k][ty * 4];
            float4 b = *(const float4*)&Bs[k][tx * 4];
            float ar[4] = {a.x, a.y, a.z, a.w};
            float br[4] = {b.x, b.y, b.z, b.w};
#pragma unroll
            for (int i = 0; i < 4; i++)
#pragma unroll
                for (int j = 0; j < 4; j++) acc[i][j] = fmaf(ar[i], br[j], acc[i][j]);
        }
        __syncthreads();
    }
    float4 bb = make_float4(0.f, 0.f, 0.f, 0.f);
    if (bias) bb = *(const float4*)&bias[n0 + tx * 4];
#pragma unroll
    for (int i = 0; i < 4; i++) {
        int m = m0 + ty * 4 + i;
        if (m >= M) continue;
        float4 o = make_float4(acc[i][0] + bb.x, acc[i][1] + bb.y,
                               acc[i][2] + bb.z, acc[i][3] + bb.w);
        *(float4*)&C[m * N + n0 + tx * 4] = o;
    }
}

// nodes[v] = sum_{e: dst=v} relu(Ha[v] + Hb[src] + b1)
__global__ void k_edge_nodes(const float* __restrict__ b1) {
    int w = blockIdx.x * 8 + (threadIdx.x >> 5);
    if (w >= NN) return;
    int l4 = (threadIdx.x & 31) * 4;
    float4 ha = *(const float4*)&d_HaHb[w * 256 + l4];
    float4 bb = *(const float4*)&b1[l4];
    ha.x += bb.x; ha.y += bb.y; ha.z += bb.z; ha.w += bb.w;
    float4 acc = make_float4(0.f, 0.f, 0.f, 0.f);
    int e = d_off[w], end = d_off[w + 1];
#pragma unroll 2
    for (; e < end; e++) {
        int s = d_adj[e];
        float4 hb = *(const float4*)&d_HaHb[s * 256 + 128 + l4];
        acc.x += fmaxf(ha.x + hb.x, 0.f);
        acc.y += fmaxf(ha.y + hb.y, 0.f);
        acc.z += fmaxf(ha.z + hb.z, 0.f);
        acc.w += fmaxf(ha.w + hb.w, 0.f);
    }
    *(float4*)&d_nodes[w * NH + l4] = acc;
}

// Pn[v] = dinv[v] * ( sum_{in-edges} dinv[src]*nodes[src] + dinv[v]*nodes[v] )
__global__ void k_prop2() {
    int w = blockIdx.x * 8 + (threadIdx.x >> 5);
    if (w >= NN) return;
    int l4 = (threadIdx.x & 31) * 4;
    float dv = d_dinv[w];
    float4 sv = *(const float4*)&d_nodes[w * NH + l4];
    float4 acc = make_float4(dv * sv.x, dv * sv.y, dv * sv.z, dv * sv.w);
    int e = d_off[w], end = d_off[w + 1];
#pragma unroll 2
    for (; e < end; e++) {
        int s = d_adj[e];
        float ds = d_dinv[s];
        float4 v0 = *(const float4*)&d_nodes[s * NH + l4];
        acc.x += ds * v0.x; acc.y += ds * v0.y;
        acc.z += ds * v0.z; acc.w += ds * v0.w;
    }
    acc.x *= dv; acc.y *= dv; acc.z *= dv; acc.w *= dv;
    *(float4*)&d_Pn[w * NH + l4] = acc;
}

// ---------------- host launcher ----------------
extern "C" void kernel_launch(void* const* d_in, const int* in_sizes, int n_in,
                              void* d_out, int out_size) {
    const float* x  = (const float*)d_in[0];
    const int*   ei = (const int*)d_in[1];
    const int    E  = in_sizes[2];
    const int* src = ei;
    const int* dst = ei + E;
    const float* Wi = (const float*)d_in[4];
    const float* bi = (const float*)d_in[5];
    const float* Wf = (const float*)d_in[6];
    const float* bf = (const float*)d_in[7];
    const float* Wo = (const float*)d_in[8];
    const float* bo = (const float*)d_in[9];
    const float* Wg = (const float*)d_in[10];
    const float* bg = (const float*)d_in[11];
    const float* W1 = (const float*)d_in[12];
    const float* b1 = (const float*)d_in[13];
    const float* Wc = (const float*)d_in[14];
    const float* bc = (const float*)d_in[15];
    float* out = (float*)d_out;

    k_init<<<(NN * NH + 255) / 256, 256>>>();
    k_deg<<<(E + 255) / 256, 256>>>(dst, E);
    k_dinv<<<(NN + 255) / 256, 256>>>();
    k_scan<<<1, 1024>>>(E);
    k_fill<<<(E + 255) / 256, 256>>>(src, dst, E);
    k_pack<<<(KTOT * NG + NH * 256 + NH * NOUT + 255) / 256, 256>>>(
        Wi, Wf, Wo, Wg, bi, bf, bo, bg, W1, Wc);
    k_px<<<TT * NN / 8, 256>>>(x);

    dim3 gg_grid((NN + 63) / 64, 2);
    for (int t = 0; t < TT; t++) {
        k_prop<<<NN / 8, 256>>>();
        k_gg<<<gg_grid, 256>>>(t);
    }

    k_gemm<<<dim3((NN + 63) / 64, 4), 256>>>(0, nullptr, nullptr, NN, NH, 256);
    k_edge_nodes<<<NN / 8, 256>>>(b1);
    k_prop2<<<NN / 8, 256>>>();
    k_gemm<<<dim3((NN + 63) / 64, 1), 256>>>(1, bc, out, NN, NH, NOUT);
}

// round 4
// speedup vs baseline: 1.2878x; 1.2878x over previous
#include <cuda_runtime.h>
#include <cuda_bf16.h>
#include <cstdint>

typedef unsigned long long ull;

#define NN   10000
#define TT   64
#define NIN  64
#define NH   128
#define NOUT 64
#define KTOT 192
#define EMAX 160000
#define MT   79                 // ceil(10000/128) M tiles
#define GG_SMEM 67584           // max(2 stage bufs 64KB, Cs 128*132*4)

// ---------------- device scratch ----------------
__device__ float d_dinv[NN];
__device__ int   d_deg[NN];
__device__ int   d_off[NN + 1];
__device__ int   d_fill[NN];
__device__ int   d_adj[EMAX];
__device__ __nv_bfloat16 d_Pxh[(size_t)TT * NN * NIN];
__device__ __nv_bfloat16 d_Pxl[(size_t)TT * NN * NIN];
__device__ __nv_bfloat16 d_Phh[NN * NH];
__device__ __nv_bfloat16 d_Phl[NN * NH];
__device__ float d_h[NN * NH];
__device__ float d_c[NN * NH];
__device__ float d_hs[NN * NH];
__device__ __nv_bfloat16 d_Wpk[2 * 4 * 3 * 128 * 64];  // [split][ns][chunk][row128][k64]
__device__ float d_bpk[512];                            // [ns][jloc*4+g]
__device__ float d_W1p[NH * 256];
__device__ float d_Wcp[NH * NOUT];
__device__ float d_HaHb[NN * 256];
__device__ float d_nodes[NN * NH];
__device__ float d_Pn[NN * NH];

// ---------------- helpers ----------------
__device__ __forceinline__ uint32_t smem_u32(const void* p) {
    uint32_t a;
    asm("{ .reg .u64 t; cvta.to.shared.u64 t, %1; cvt.u32.u64 %0, t; }" : "=r"(a) : "l"(p));
    return a;
}
__device__ __forceinline__ void cp16(uint32_t dst, const void* src, uint32_t srcsize) {
    asm volatile("cp.async.ca.shared.global [%0], [%1], 16, %2;"
                 :: "r"(dst), "l"(src), "r"(srcsize) : "memory");
}
__device__ __forceinline__ void cp_commit() {
    asm volatile("cp.async.commit_group;" ::: "memory");
}
__device__ __forceinline__ void cp_wait1() {
    asm volatile("cp.async.wait_group 1;" ::: "memory");
}
__device__ __forceinline__ void cp_wait0() {
    asm volatile("cp.async.wait_group 0;" ::: "memory");
}
__device__ __forceinline__ void ldsm4(uint32_t* r, uint32_t addr) {
    asm volatile("ldmatrix.sync.aligned.m8n8.x4.shared.b16 {%0,%1,%2,%3}, [%4];"
                 : "=r"(r[0]), "=r"(r[1]), "=r"(r[2]), "=r"(r[3]) : "r"(addr));
}
__device__ __forceinline__ void mma16816(float* c, const uint32_t* a, const uint32_t* b) {
    asm volatile("mma.sync.aligned.m16n8k16.row.col.f32.bf16.bf16.f32 "
                 "{%0,%1,%2,%3}, {%4,%5,%6,%7}, {%8,%9}, {%0,%1,%2,%3};"
                 : "+f"(c[0]), "+f"(c[1]), "+f"(c[2]), "+f"(c[3])
                 : "r"(a[0]), "r"(a[1]), "r"(a[2]), "r"(a[3]), "r"(b[0]), "r"(b[1]));
}
__device__ __forceinline__ float sigf(float x) { return 1.0f / (1.0f + __expf(-x)); }

// ---------------- setup kernels ----------------
__global__ void k_init() {
    int i = blockIdx.x * blockDim.x + threadIdx.x;
    if (i < NN * NH) { d_c[i] = 0.f; d_hs[i] = 0.f; }
    if (i < NN)      { d_deg[i] = 1; d_fill[i] = 0; }
}

__global__ void k_deg(const int* __restrict__ dst, int E) {
    int i = blockIdx.x * blockDim.x + threadIdx.x;
    if (i < E) atomicAdd(&d_deg[dst[i]], 1);
}

__global__ void k_dinv() {
    int i = blockIdx.x * blockDim.x + threadIdx.x;
    if (i < NN) d_dinv[i] = rsqrtf((float)d_deg[i]);
}

__global__ void k_scan(int E) {
    __shared__ int ssum[1024];
    int tid = threadIdx.x;
    int loc[10]; int run = 0;
#pragma unroll
    for (int i = 0; i < 10; i++) {
        int v = tid * 10 + i;
        int c = (v < NN) ? (d_deg[v] - 1) : 0;
        loc[i] = run; run += c;
    }
    ssum[tid] = run; __syncthreads();
    for (int off = 1; off < 1024; off <<= 1) {
        int t = (tid >= off) ? ssum[tid - off] : 0;
        __syncthreads();
        ssum[tid] += t;
        __syncthreads();
    }
    int base = (tid == 0) ? 0 : ssum[tid - 1];
#pragma unroll
    for (int i = 0; i < 10; i++) {
        int v = tid * 10 + i;
        if (v < NN) d_off[v] = base + loc[i];
    }
    if (tid == 0) d_off[NN] = E;
}

__global__ void k_fill(const int* __restrict__ src, const int* __restrict__ dst, int E) {
    int i = blockIdx.x * blockDim.x + threadIdx.x;
    if (i < E) {
        int v = dst[i];
        int p = d_off[v] + atomicAdd(&d_fill[v], 1);
        d_adj[p] = src[i];
    }
}

// pack weights: bf16 split + [j*4+g] column order; W1p/Wcp for decoder
// d_Wpk layout: [s(2)][ns(4)][c(3)][row(128)][kk(64)]  (strides 98304/24576/8192/64)
#define WPK_N   196608
#define BPK_END (WPK_N + 512)
#define W1P_END (BPK_END + NH * 256)
#define WCP_END (W1P_END + NH * NOUT)
__global__ void k_pack(const float* __restrict__ Wi, const float* __restrict__ Wf,
                       const float* __restrict__ Wo, const float* __restrict__ Wg,
                       const float* __restrict__ bi, const float* __restrict__ bf,
                       const float* __restrict__ bo, const float* __restrict__ bg,
                       const float* __restrict__ W1, const float* __restrict__ Wc) {
    int idx = blockIdx.x * blockDim.x + threadIdx.x;
    if (idx < WPK_N) {
        int s  = idx / 98304;
        int r  = idx % 98304;
        int ns = r / 24576;  r %= 24576;
        int c  = r / 8192;   r %= 8192;
        int row = r / 64;    int kk = r % 64;
        int j = ns * 32 + (row >> 2), g = row & 3, k = c * 64 + kk;
        const float* W = (g == 0) ? Wi : (g == 1) ? Wf : (g == 2) ? Wo : Wg;
        float w = W[j * KTOT + k];
        __nv_bfloat16 hi = __float2bfloat16(w);
        d_Wpk[idx] = (s == 0) ? hi : __float2bfloat16(w - __bfloat162float(hi));
    } else if (idx < BPK_END) {
        int i = idx - WPK_N;
        int rr = i & 127;
        int j = (i >> 7) * 32 + (rr >> 2), g = rr & 3;
        const float* b = (g == 0) ? bi : (g == 1) ? bf : (g == 2) ? bo : bg;
        d_bpk[i] = b[j];
    } else if (idx < W1P_END) {
        int r = idx - BPK_END;
        int k = r / 256, cc = r % 256;
        d_W1p[r] = W1[(cc & 127) * 256 + (cc >> 7) * 128 + k];
    } else if (idx < WCP_END) {
        int r = idx - W1P_END;
        int k = r / NOUT, j = r % NOUT;
        d_Wcp[r] = Wc[j * NH + k];
    }
}

// Px = P @ x_t for all t, output bf16 hi/lo split
__global__ void k_px(const float* __restrict__ x) {
    int w = blockIdx.x * 8 + (threadIdx.x >> 5);
    int t = w / NN, v = w - t * NN;
    int l2 = (threadIdx.x & 31) * 2;
    const float* xt = x + (size_t)t * NN * NIN;
    float2 a = make_float2(0.f, 0.f);
    int e = d_off[v], end = d_off[v + 1];
#pragma unroll 4
    for (; e < end; e++) {
        int s = d_adj[e];
        float ds = d_dinv[s];
        float2 xv = *(const float2*)&xt[s * NIN + l2];
        a.x += ds * xv.x; a.y += ds * xv.y;
    }
    float dv = d_dinv[v];
    float2 xs = *(const float2*)&xt[v * NIN + l2];
    a.x = dv * (a.x + dv * xs.x);
    a.y = dv * (a.y + dv * xs.y);
    __nv_bfloat16 h0 = __float2bfloat16(a.x), h1 = __float2bfloat16(a.y);
    __nv_bfloat16 l0 = __float2bfloat16(a.x - __bfloat162float(h0));
    __nv_bfloat16 l1 = __float2bfloat16(a.y - __bfloat162float(h1));
    size_t o = ((size_t)t * NN + v) * NIN + l2;
    *(__nv_bfloat162*)&d_Pxh[o] = __halves2bfloat162(h0, h1);
    *(__nv_bfloat162*)&d_Pxl[o] = __halves2bfloat162(l0, l1);
}

// Ph = P @ h (from pre-scaled hs), output bf16 hi/lo split
__global__ void k_prop() {
    int w = blockIdx.x * 8 + (threadIdx.x >> 5);
    if (w >= NN) return;
    int l4 = (threadIdx.x & 31) * 4;
    float4 acc = *(const float4*)&d_hs[w * NH + l4];
    int e = d_off[w], end = d_off[w + 1];
    for (; e + 1 < end; e += 2) {
        int s0 = d_adj[e], s1 = d_adj[e + 1];
        float4 v0 = *(const float4*)&d_hs[s0 * NH + l4];
        float4 v1 = *(const float4*)&d_hs[s1 * NH + l4];
        acc.x += v0.x + v1.x; acc.y += v0.y + v1.y;
        acc.z += v0.z + v1.z; acc.w += v0.w + v1.w;
    }
    if (e < end) {
        int s0 = d_adj[e];
        float4 v0 = *(const float4*)&d_hs[s0 * NH + l4];
        acc.x += v0.x; acc.y += v0.y; acc.z += v0.z; acc.w += v0.w;
    }
    float dv = d_dinv[w];
    acc.x *= dv; acc.y *= dv; acc.z *= dv; acc.w *= dv;
    __nv_bfloat16 h0 = __float2bfloat16(acc.x), h1 = __float2bfloat16(acc.y);
    __nv_bfloat16 h2 = __float2bfloat16(acc.z), h3 = __float2bfloat16(acc.w);
    __nv_bfloat16 l0 = __float2bfloat16(acc.x - __bfloat162float(h0));
    __nv_bfloat16 l1 = __float2bfloat16(acc.y - __bfloat162float(h1));
    __nv_bfloat16 l2b = __float2bfloat16(acc.z - __bfloat162float(h2));
    __nv_bfloat16 l3 = __float2bfloat16(acc.w - __bfloat162float(h3));
    int o = w * NH + l4;
    *(__nv_bfloat162*)&d_Phh[o]     = __halves2bfloat162(h0, h1);
    *(__nv_bfloat162*)&d_Phh[o + 2] = __halves2bfloat162(h2, h3);
    *(__nv_bfloat162*)&d_Phl[o]     = __halves2bfloat162(l0, l1);
    *(__nv_bfloat162*)&d_Phl[o + 2] = __halves2bfloat162(l2b, l3);
}

// ---------------- step GEMM: mma.sync bf16, 3-pass split, fused LSTM epilogue ----
// chunk ch (0..8): pass p=ch/3 (0:hh 1:hl 2:lh), c=ch%3 (0:Px, 1:Ph[0:64], 2:Ph[64:128])
__device__ __forceinline__ void gg_load_stage(char* smem, int st, int ch, int t, int m0,
                                              int ns, int tid) {
    int p = ch / 3, c = ch - p * 3;
    int sa = (p == 2), sb = (p == 1);
    const __nv_bfloat16* Ag;
    int ars;
    if (c == 0) { Ag = (sa ? d_Pxl : d_Pxh) + ((size_t)t * NN + m0) * 64; ars = 64; }
    else        { Ag = (sa ? d_Phl : d_Phh) + (size_t)m0 * 128 + (c - 1) * 64; ars = 128; }
    const __nv_bfloat16* Bg = d_Wpk + ((size_t)(sb * 4 + ns) * 3 + c) * 8192;
    uint32_t sA = smem_u32(smem) + st * 32768;
    uint32_t sB = sA + 16384;
#pragma unroll
    for (int it = 0; it < 4; it++) {
        int idx = tid + it * 256;
        int row = idx >> 3, kg = idx & 7;
        uint32_t soff = row * 128 + ((kg ^ (row & 7)) << 4);
        cp16(sA + soff, Ag + (size_t)row * ars + kg * 8, (m0 + row < NN) ? 16 : 0);
        cp16(sB + soff, Bg + row * 64 + kg * 8, 16);
    }
    cp_commit();
}

__global__ void __launch_bounds__(256, 2) k_gg(int t, int last) {
    extern __shared__ char smem[];
    const int tid = threadIdx.x, lane = tid & 31, wid = tid >> 5;
    const int m0 = blockIdx.x * 128, ns = blockIdx.y;
    const int wm = (wid & 1) * 64, wn = (wid >> 1) * 32;
    const int g = lane >> 3, lr = lane & 7;

    float acc[4][4][4];
#pragma unroll
    for (int i = 0; i < 4; i++)
#pragma unroll
        for (int j = 0; j < 4; j++)
#pragma unroll
            for (int q = 0; q < 4; q++) acc[i][j][q] = 0.f;

    gg_load_stage(smem, 0, 0, t, m0, ns, tid);
    gg_load_stage(smem, 1, 1, t, m0, ns, tid);

    for (int ch = 0; ch < 9; ch++) {
        if (ch < 7) cp_wait1(); else cp_wait0();
        __syncthreads();
        uint32_t sA = smem_u32(smem) + (ch & 1) * 32768;
        uint32_t sB = sA + 16384;
#pragma unroll
        for (int ks = 0; ks < 4; ks++) {
            uint32_t af[4][4], bfr[2][4];
#pragma unroll
            for (int mt = 0; mt < 4; mt++) {
                int arow = wm + mt * 16 + (g & 1) * 8 + lr;
                int akg = ks * 2 + (g >> 1);
                ldsm4(af[mt], sA + arow * 128 + ((akg ^ (arow & 7)) << 4));
            }
#pragma unroll
            for (int nsub = 0; nsub < 2; nsub++) {
                int brow = wn + nsub * 16 + (g >> 1) * 8 + lr;
                int bkg = ks * 2 + (g & 1);
                ldsm4(bfr[nsub], sB + brow * 128 + ((bkg ^ (brow & 7)) << 4));
            }
#pragma unroll
            for (int mt = 0; mt < 4; mt++)
#pragma unroll
                for (int nt = 0; nt < 4; nt++)
                    mma16816(acc[mt][nt], af[mt], &bfr[nt >> 1][(nt & 1) * 2]);
        }
        __syncthreads();
        if (ch + 2 < 9) gg_load_stage(smem, ch & 1, ch + 2, t, m0, ns, tid);
        else cp_commit();   // keep group counts consistent
    }

    // stage accumulators to smem [128][132]
    __syncthreads();
    float* Cs = (float*)smem;
#pragma unroll
    for (int mt = 0; mt < 4; mt++)
#pragma unroll
        for (int nt = 0; nt < 4; nt++) {
            int r = wm + mt * 16 + (lane >> 2);
            int col = wn + nt * 8 + (lane & 3) * 2;
            *(float2*)&Cs[r * 132 + col]       = make_float2(acc[mt][nt][0], acc[mt][nt][1]);
            *(float2*)&Cs[(r + 8) * 132 + col] = make_float2(acc[mt][nt][2], acc[mt][nt][3]);
        }
    __syncthreads();

    // fused LSTM epilogue: 4096 cells, 16 per thread
#pragma unroll
    for (int it = 0; it < 16; it++) {
        int idx = it * 256 + tid;
        int mloc = idx >> 5, jloc = idx & 31;
        int m = m0 + mloc;
        if (m >= NN) continue;
        float4 pre = *(const float4*)&Cs[mloc * 132 + jloc * 4];
        const float* bp = &d_bpk[ns * 128 + jloc * 4];
        float i_ = sigf(pre.x + bp[0]);
        float f_ = sigf(pre.y + bp[1]);
        float o_ = sigf(pre.z + bp[2]);
        float g_ = tanhf(pre.w + bp[3]);
        int ci = m * NH + ns * 32 + jloc;
        float cn = f_ * d_c[ci] + i_ * g_;
        float hh = o_ * tanhf(cn);
        d_c[ci] = cn;
        d_hs[ci] = d_dinv[m] * hh;
        if (last) d_h[ci] = hh;
    }
}

// ---------------- decoder ----------------
__global__ void k_gemm(int sel, const float* __restrict__ bias, float* __restrict__ Cout,
                       int M, int K, int N) {
    __shared__ __align__(16) float As[16][64];
    __shared__ __align__(16) float Bs[16][64];
    const float* A = sel ? d_Pn  : d_h;
    const float* B = sel ? d_Wcp : d_W1p;
    float*       C = sel ? Cout  : d_HaHb;
    int tid = threadIdx.x;
    int tx = tid & 15, ty = tid >> 4;
    int m0 = blockIdx.x * 64, n0 = blockIdx.y * 64;
    float acc[4][4] = {};
    int lrow = tid >> 2, lkp = (tid & 3) * 4;
    int bk = tid >> 4, bcc = (tid & 15) * 4;
    for (int kc = 0; kc < K; kc += 16) {
        float4 av = make_float4(0.f, 0.f, 0.f, 0.f);
        int grow = m0 + lrow;
        if (grow < M) av = *(const float4*)&A[grow * K + kc + lkp];
        As[lkp + 0][lrow] = av.x; As[lkp + 1][lrow] = av.y;
        As[lkp + 2][lrow] = av.z; As[lkp + 3][lrow] = av.w;
        float4 bv = *(const float4*)&B[(kc + bk) * N + n0 + bcc];
        *(float4*)&Bs[bk][bcc] = bv;
        __syncthreads();
#pragma unroll
        for (int k = 0; k < 16; k++) {
            float4 a = *(const float4*)&As[k][ty * 4];
            float4 b = *(const float4*)&Bs[k][tx * 4];
            float ar[4] = {a.x, a.y, a.z, a.w};
            float br[4] = {b.x, b.y, b.z, b.w};
#pragma unroll
            for (int i = 0; i < 4; i++)
#pragma unroll
                for (int j = 0; j < 4; j++) acc[i][j] = fmaf(ar[i], br[j], acc[i][j]);
        }
        __syncthreads();
    }
    float4 bb = make_float4(0.f, 0.f, 0.f, 0.f);
    if (bias) bb = *(const float4*)&bias[n0 + tx * 4];
#pragma unroll
    for (int i = 0; i < 4; i++) {
        int m = m0 + ty * 4 + i;
        if (m >= M) continue;
        float4 o = make_float4(acc[i][0] + bb.x, acc[i][1] + bb.y,
                               acc[i][2] + bb.z, acc[i][3] + bb.w);
        *(float4*)&C[m * N + n0 + tx * 4] = o;
    }
}

__global__ void k_edge_nodes(const float* __restrict__ b1) {
    int w = blockIdx.x * 8 + (threadIdx.x >> 5);
    if (w >= NN) return;
    int l4 = (threadIdx.x & 31) * 4;
    float4 ha = *(const float4*)&d_HaHb[w * 256 + l4];
    float4 bb = *(const float4*)&b1[l4];
    ha.x += bb.x; ha.y += bb.y; ha.z += bb.z; ha.w += bb.w;
    float4 acc = make_float4(0.f, 0.f, 0.f, 0.f);
    int e = d_off[w], end = d_off[w + 1];
#pragma unroll 2
    for (; e < end; e++) {
        int s = d_adj[e];
        float4 hb = *(const float4*)&d_HaHb[s * 256 + 128 + l4];
        acc.x += fmaxf(ha.x + hb.x, 0.f);
        acc.y += fmaxf(ha.y + hb.y, 0.f);
        acc.z += fmaxf(ha.z + hb.z, 0.f);
        acc.w += fmaxf(ha.w + hb.w, 0.f);
    }
    *(float4*)&d_nodes[w * NH + l4] = acc;
}

__global__ void k_prop2() {
    int w = blockIdx.x * 8 + (threadIdx.x >> 5);
    if (w >= NN) return;
    int l4 = (threadIdx.x & 31) * 4;
    float dv = d_dinv[w];
    float4 sv = *(const float4*)&d_nodes[w * NH + l4];
    float4 acc = make_float4(dv * sv.x, dv * sv.y, dv * sv.z, dv * sv.w);
    int e = d_off[w], end = d_off[w + 1];
#pragma unroll 2
    for (; e < end; e++) {
        int s = d_adj[e];
        float ds = d_dinv[s];
        float4 v0 = *(const float4*)&d_nodes[s * NH + l4];
        acc.x += ds * v0.x; acc.y += ds * v0.y;
        acc.z += ds * v0.z; acc.w += ds * v0.w;
    }
    acc.x *= dv; acc.y *= dv; acc.z *= dv; acc.w *= dv;
    *(float4*)&d_Pn[w * NH + l4] = acc;
}

// ---------------- host launcher ----------------
extern "C" void kernel_launch(void* const* d_in, const int* in_sizes, int n_in,
                              void* d_out, int out_size) {
    const float* x  = (const float*)d_in[0];
    const int*   ei = (const int*)d_in[1];
    const int    E  = in_sizes[2];
    const int* src = ei;
    const int* dst = ei + E;
    const float* Wi = (const float*)d_in[4];
    const float* bi = (const float*)d_in[5];
    const float* Wf = (const float*)d_in[6];
    const float* bf = (const float*)d_in[7];
    const float* Wo = (const float*)d_in[8];
    const float* bo = (const float*)d_in[9];
    const float* Wg = (const float*)d_in[10];
    const float* bg = (const float*)d_in[11];
    const float* W1 = (const float*)d_in[12];
    const float* b1 = (const float*)d_in[13];
    const float* Wc = (const float*)d_in[14];
    const float* bc = (const float*)d_in[15];
    float* out = (float*)d_out;

    static int smem_set = 0;
    if (!smem_set) {
        cudaFuncSetAttribute(k_gg, cudaFuncAttributeMaxDynamicSharedMemorySize, GG_SMEM);
        smem_set = 1;
    }

    k_init<<<(NN * NH + 255) / 256, 256>>>();
    k_deg<<<(E + 255) / 256, 256>>>(dst, E);
    k_dinv<<<(NN + 255) / 256, 256>>>();
    k_scan<<<1, 1024>>>(E);
    k_fill<<<(E + 255) / 256, 256>>>(src, dst, E);
    k_pack<<<(WCP_END + 255) / 256, 256>>>(Wi, Wf, Wo, Wg, bi, bf, bo, bg, W1, Wc);
    k_px<<<TT * NN / 8, 256>>>(x);

    for (int t = 0; t < TT; t++) {
        k_prop<<<NN / 8, 256>>>();
        k_gg<<<dim3(MT, 4), 256, GG_SMEM>>>(t, t == TT - 1);
    }

    k_gemm<<<dim3((NN + 63) / 64, 4), 256>>>(0, nullptr, nullptr, NN, NH, 256);
    k_edge_nodes<<<NN / 8, 256>>>(b1);
    k_prop2<<<NN / 8, 256>>>();
    k_gemm<<<dim3((NN + 63) / 64, 1), 256>>>(1, bc, out, NN, NH, NOUT);
}